// round 7
// baseline (speedup 1.0000x reference)
#include <cuda_runtime.h>
#include <cstdint>
#include <cstddef>

// Pixel_RNNcontrol: h_t = tanh(x_t @ W_ih^T + h_{t-1} @ W_hh^T + b), out = sigmoid(10 h_t)
// T=128, B=262144, I=H=2.
//
// R7: TMA (cp.async.bulk / UBLKCP) load pipeline. Each CTA stages x[t] through
// an 8-deep smem ring (4KB/stage = 256 threads x float4), one bulk copy per
// timestep issued by thread 0, completion tracked by per-stage mbarrier with
// expect_tx. Removes all per-thread LDG issue overhead and register prefetch
// buffers; DRAM sees clean 4KB bursts. Stores remain STG.128 .cs.
// Recurrence tanh exact (EX2+RCP); output sigmoid via HW tanh.approx.

#define TPB 256
#define NST 8   // ring stages; 8 * 4KB = 32KB smem

__device__ __forceinline__ float exact_tanh(float z) {
    float k = 2.885390082f * z;        // 2*log2(e) * z
    float e;
    asm("ex2.approx.f32 %0, %1;" : "=f"(e) : "f"(k));
    float r;
    float d = e + 1.0f;
    asm("rcp.approx.f32 %0, %1;" : "=f"(r) : "f"(d));
    return fmaf(-2.0f, r, 1.0f);
}

__device__ __forceinline__ float sig10(float h) {
    float t;
    float a = 5.0f * h;
    asm("tanh.approx.f32 %0, %1;" : "=f"(t) : "f"(a));
    return fmaf(0.5f, t, 0.5f);
}

__device__ __forceinline__ uint32_t smem_u32(const void* p) {
    return (uint32_t)__cvta_generic_to_shared(p);
}

__device__ __forceinline__ void mbar_init(uint32_t mbar, uint32_t count) {
    asm volatile("mbarrier.init.shared.b64 [%0], %1;" :: "r"(mbar), "r"(count) : "memory");
}

__device__ __forceinline__ void mbar_expect_tx(uint32_t mbar, uint32_t bytes) {
    asm volatile("mbarrier.arrive.expect_tx.shared.b64 _, [%0], %1;"
                 :: "r"(mbar), "r"(bytes) : "memory");
}

__device__ __forceinline__ void bulk_ld(uint32_t smem_dst, const void* gsrc,
                                        uint32_t bytes, uint32_t mbar) {
    asm volatile("cp.async.bulk.shared::cta.global.mbarrier::complete_tx::bytes "
                 "[%0], [%1], %2, [%3];"
                 :: "r"(smem_dst), "l"(gsrc), "r"(bytes), "r"(mbar) : "memory");
}

__device__ __forceinline__ void mbar_wait(uint32_t mbar, uint32_t parity) {
    uint32_t done;
    asm volatile(
        "{\n\t.reg .pred p;\n\t"
        "mbarrier.try_wait.parity.acquire.cta.shared::cta.b64 p, [%1], %2;\n\t"
        "selp.b32 %0, 1, 0, p;\n\t}"
        : "=r"(done) : "r"(mbar), "r"(parity) : "memory");
    if (!done) {
        asm volatile(
            "{\n\t.reg .pred P1;\n\t"
            "WAIT_LOOP_%=:\n\t"
            "mbarrier.try_wait.parity.acquire.cta.shared::cta.b64 P1, [%0], %1, 0x989680;\n\t"
            "@P1 bra.uni WAIT_DONE_%=;\n\t"
            "bra.uni WAIT_LOOP_%=;\n\t"
            "WAIT_DONE_%=:\n\t}"
            :: "r"(mbar), "r"(parity) : "memory");
    }
}

// TMA-pipelined kernel: requires npairs % TPB == 0 (true for B=262144).
__global__ void __launch_bounds__(TPB)
rnn_tma_kernel(const float4* __restrict__ x4,
               const float4* __restrict__ h04,
               const float*  __restrict__ Wih,
               const float*  __restrict__ Whh,
               const float*  __restrict__ bih,
               const float*  __restrict__ bhh,
               float4* __restrict__ out4,
               float4* __restrict__ hout4,
               int T, int npairs)
{
    __shared__ alignas(128) float4 stage[NST][TPB];
    __shared__ alignas(8)  uint64_t mbar_s[NST];

    const int tid = threadIdx.x;
    const int p0  = blockIdx.x * TPB;       // block's first pair index
    const int p   = p0 + tid;

    const uint32_t mb0 = smem_u32(&mbar_s[0]);

    if (tid == 0) {
        #pragma unroll
        for (int s = 0; s < NST; ++s) mbar_init(mb0 + 8u * s, 1);
    }
    __syncthreads();

    // Prime: issue bulk loads for t = 0..NST-1
    if (tid == 0) {
        #pragma unroll
        for (int s = 0; s < NST; ++s) {
            if (s < T) {
                uint32_t mb = mb0 + 8u * s;
                mbar_expect_tx(mb, TPB * 16u);
                bulk_ld(smem_u32(&stage[s][0]), x4 + (size_t)s * npairs + p0,
                        TPB * 16u, mb);
            }
        }
    }

    const float a00 = Wih[0], a01 = Wih[1], a10 = Wih[2], a11 = Wih[3];
    const float w00 = Whh[0], w01 = Whh[1], w10 = Whh[2], w11 = Whh[3];
    const float b0 = bih[0] + bhh[0];
    const float b1 = bih[1] + bhh[1];

    float4 hv = h04[p];
    float hA0 = hv.x, hA1 = hv.y;
    float hB0 = hv.z, hB1 = hv.w;

    float4* ost = out4 + p;

    for (int t = 0; t < T; ++t) {
        const int      slot = t & (NST - 1);
        const uint32_t ph   = (t / NST) & 1;
        const uint32_t mb   = mb0 + 8u * slot;

        mbar_wait(mb, ph);
        float4 xv = stage[slot][tid];

        // All threads must have read the slot before thread 0 reissues it.
        __syncthreads();

        int tp = t + NST;
        if (tid == 0 && tp < T) {
            mbar_expect_tx(mb, TPB * 16u);
            bulk_ld(smem_u32(&stage[slot][0]), x4 + (size_t)tp * npairs + p0,
                    TPB * 16u, mb);
        }

        float zA0 = fmaf(a00, xv.x, fmaf(a01, xv.y, fmaf(w00, hA0, fmaf(w01, hA1, b0))));
        float zA1 = fmaf(a10, xv.x, fmaf(a11, xv.y, fmaf(w10, hA0, fmaf(w11, hA1, b1))));
        float zB0 = fmaf(a00, xv.z, fmaf(a01, xv.w, fmaf(w00, hB0, fmaf(w01, hB1, b0))));
        float zB1 = fmaf(a10, xv.z, fmaf(a11, xv.w, fmaf(w10, hB0, fmaf(w11, hB1, b1))));

        hA0 = exact_tanh(zA0);
        hA1 = exact_tanh(zA1);
        hB0 = exact_tanh(zB0);
        hB1 = exact_tanh(zB1);

        float4 o;
        o.x = sig10(hA0);
        o.y = sig10(hA1);
        o.z = sig10(hB0);
        o.w = sig10(hB1);
        __stcs(ost, o);
        ost += npairs;
    }

    float4 hf;
    hf.x = hA0; hf.y = hA1; hf.z = hB0; hf.w = hB1;
    hout4[p] = hf;
}

// Fallback (R3-style register pipeline) for shapes where npairs % TPB != 0.
#define PF 4
__global__ void __launch_bounds__(256)
rnn_ldg_kernel(const float4* __restrict__ x4,
               const float4* __restrict__ h04,
               const float*  __restrict__ Wih,
               const float*  __restrict__ Whh,
               const float*  __restrict__ bih,
               const float*  __restrict__ bhh,
               float4* __restrict__ out4,
               float4* __restrict__ hout4,
               int T, int npairs)
{
    int p = blockIdx.x * blockDim.x + threadIdx.x;
    if (p >= npairs) return;

    const float a00 = Wih[0], a01 = Wih[1], a10 = Wih[2], a11 = Wih[3];
    const float w00 = Whh[0], w01 = Whh[1], w10 = Whh[2], w11 = Whh[3];
    const float b0 = bih[0] + bhh[0];
    const float b1 = bih[1] + bhh[1];

    float4 hv = h04[p];
    float hA0 = hv.x, hA1 = hv.y;
    float hB0 = hv.z, hB1 = hv.w;

    float4 buf[PF];
    #pragma unroll
    for (int i = 0; i < PF; ++i) {
        int ti = (i < T) ? i : (T - 1);
        buf[i] = __ldcs(&x4[(size_t)ti * npairs + p]);
    }
    const float4* xld = x4 + (size_t)PF * npairs + p;
    float4*       ost = out4 + p;

    int t = 0;
    for (; t + PF <= T; t += PF) {
        #pragma unroll
        for (int i = 0; i < PF; ++i) {
            float4 xv = buf[i];
            if (t + i + PF < T) buf[i] = __ldcs(xld);
            xld += npairs;
            float zA0 = fmaf(a00, xv.x, fmaf(a01, xv.y, fmaf(w00, hA0, fmaf(w01, hA1, b0))));
            float zA1 = fmaf(a10, xv.x, fmaf(a11, xv.y, fmaf(w10, hA0, fmaf(w11, hA1, b1))));
            float zB0 = fmaf(a00, xv.z, fmaf(a01, xv.w, fmaf(w00, hB0, fmaf(w01, hB1, b0))));
            float zB1 = fmaf(a10, xv.z, fmaf(a11, xv.w, fmaf(w10, hB0, fmaf(w11, hB1, b1))));
            hA0 = exact_tanh(zA0); hA1 = exact_tanh(zA1);
            hB0 = exact_tanh(zB0); hB1 = exact_tanh(zB1);
            float4 o;
            o.x = sig10(hA0); o.y = sig10(hA1); o.z = sig10(hB0); o.w = sig10(hB1);
            __stcs(ost, o);
            ost += npairs;
        }
    }
    for (int i = 0; t < T; ++t, ++i) {
        float4 xv = buf[i];
        float zA0 = fmaf(a00, xv.x, fmaf(a01, xv.y, fmaf(w00, hA0, fmaf(w01, hA1, b0))));
        float zA1 = fmaf(a10, xv.x, fmaf(a11, xv.y, fmaf(w10, hA0, fmaf(w11, hA1, b1))));
        float zB0 = fmaf(a00, xv.z, fmaf(a01, xv.w, fmaf(w00, hB0, fmaf(w01, hB1, b0))));
        float zB1 = fmaf(a10, xv.z, fmaf(a11, xv.w, fmaf(w10, hB0, fmaf(w11, hB1, b1))));
        hA0 = exact_tanh(zA0); hA1 = exact_tanh(zA1);
        hB0 = exact_tanh(zB0); hB1 = exact_tanh(zB1);
        float4 o;
        o.x = sig10(hA0); o.y = sig10(hA1); o.z = sig10(hB0); o.w = sig10(hB1);
        __stcs(ost, o);
        ost += npairs;
    }

    float4 hf;
    hf.x = hA0; hf.y = hA1; hf.z = hB0; hf.w = hB1;
    hout4[p] = hf;
}

extern "C" void kernel_launch(void* const* d_in, const int* in_sizes, int n_in,
                              void* d_out, int out_size)
{
    const float* x   = (const float*)d_in[0];   // (T, B, 2)
    const float* h0  = (const float*)d_in[1];   // (1, B, 2)
    const float* Wih = (const float*)d_in[2];
    const float* Whh = (const float*)d_in[3];
    const float* bih = (const float*)d_in[4];
    const float* bhh = (const float*)d_in[5];

    const int BH = in_sizes[1];                 // B * 2
    const int B  = BH / 2;
    const int T  = in_sizes[0] / BH;

    float* out  = (float*)d_out;
    float* hout = out + ((size_t)out_size - (size_t)BH);

    const int npairs = B / 2;

    if (npairs % TPB == 0) {
        const int blocks = npairs / TPB;
        rnn_tma_kernel<<<blocks, TPB>>>(
            (const float4*)x, (const float4*)h0,
            Wih, Whh, bih, bhh,
            (float4*)out, (float4*)hout, T, npairs);
    } else {
        const int blocks = (npairs + 255) / 256;
        rnn_ldg_kernel<<<blocks, 256>>>(
            (const float4*)x, (const float4*)h0,
            Wih, Whh, bih, bhh,
            (float4*)out, (float4*)hout, T, npairs);
    }
}

// round 8
// speedup vs baseline: 1.0750x; 1.0750x over previous
#include <cuda_runtime.h>
#include <cstddef>

// Pixel_RNNcontrol: h_t = tanh(x_t @ W_ih^T + h_{t-1} @ W_hh^T + b), out = sigmoid(10 h_t)
// T=128, B=262144, I=H=2. One thread handles 2 batch elements (float4 lanes).
//
// R8: R3's proven PF=4 register pipeline (90.7us) + prefetch.global.L2 issued
// PFL2 steps ahead. DRAM->L2 depth grows to ~12 steps/warp at zero register
// cost; LDGs then hit L2 (~234cyc) instead of DRAM (~580cyc), so PF=4 covers
// fully. TMA (R7), smem cp.async (R5), and deep register pipelines (R4) all
// regressed; this is the remaining zero-overhead depth mechanism.

#define PF    4    // register prefetch depth (L2 -> reg)
#define PFL2  12   // L2 prefetch distance (DRAM -> L2)

__device__ __forceinline__ float exact_tanh(float z) {
    // tanh(z) = 1 - 2/(1 + e^{2z}); z bounded (|z| <~ 7) -> no overflow
    float k = 2.885390082f * z;        // 2*log2(e) * z
    float e;
    asm("ex2.approx.f32 %0, %1;" : "=f"(e) : "f"(k));
    float r;
    float d = e + 1.0f;
    asm("rcp.approx.f32 %0, %1;" : "=f"(r) : "f"(d));
    return fmaf(-2.0f, r, 1.0f);
}

__device__ __forceinline__ float sig10(float h) {
    // sigmoid(10h) = 0.5 + 0.5*tanh(5h); HW tanh -> 1 MUFU, error non-accumulating
    float t;
    float a = 5.0f * h;
    asm("tanh.approx.f32 %0, %1;" : "=f"(t) : "f"(a));
    return fmaf(0.5f, t, 0.5f);
}

__device__ __forceinline__ void prefetch_l2(const void* p) {
    asm volatile("prefetch.global.L2 [%0];" :: "l"(p));
}

__global__ void __launch_bounds__(256)
rnn_sigmoid_kernel(const float4* __restrict__ x4,
                   const float4* __restrict__ h04,
                   const float*  __restrict__ Wih,
                   const float*  __restrict__ Whh,
                   const float*  __restrict__ bih,
                   const float*  __restrict__ bhh,
                   float4* __restrict__ out4,
                   float4* __restrict__ hout4,
                   int T, int npairs)
{
    int p = blockIdx.x * blockDim.x + threadIdx.x;
    if (p >= npairs) return;

    // 2x2 weights (row-major). z = x @ W^T  ->  z0 = W[0][0]*x0 + W[0][1]*x1
    const float a00 = Wih[0], a01 = Wih[1], a10 = Wih[2], a11 = Wih[3];
    const float w00 = Whh[0], w01 = Whh[1], w10 = Whh[2], w11 = Whh[3];
    const float b0 = bih[0] + bhh[0];
    const float b1 = bih[1] + bhh[1];

    float4 hv = h04[p];
    float hA0 = hv.x, hA1 = hv.y;   // batch element A
    float hB0 = hv.z, hB1 = hv.w;   // batch element B

    // Warm L2 ahead of the register pipeline.
    #pragma unroll
    for (int s = PF; s < PFL2; ++s) {
        if (s < T) prefetch_l2(&x4[(size_t)s * npairs + p]);
    }

    // Prime the register pipeline: PF loads in flight before the loop.
    float4 buf[PF];
    #pragma unroll
    for (int i = 0; i < PF; ++i) {
        int ti = (i < T) ? i : (T - 1);
        buf[i] = __ldcs(&x4[(size_t)ti * npairs + p]);
    }

    const float4* xld = x4 + (size_t)PF * npairs + p;     // next LDG addr (t = PF)
    const float4* xpf = x4 + (size_t)PFL2 * npairs + p;   // next L2-prefetch addr
    float4*       ost = out4 + p;                          // store addr (t = 0)

    int t = 0;
    for (; t + PF <= T; t += PF) {
        #pragma unroll
        for (int i = 0; i < PF; ++i) {
            float4 xv = buf[i];

            // DRAM -> L2, PFL2 steps ahead (no register cost)
            if (t + i + PFL2 < T) prefetch_l2(xpf);
            xpf += npairs;

            // L2 -> reg, PF steps ahead
            if (t + i + PF < T) buf[i] = __ldcs(xld);
            xld += npairs;

            float zA0 = fmaf(a00, xv.x, fmaf(a01, xv.y, fmaf(w00, hA0, fmaf(w01, hA1, b0))));
            float zA1 = fmaf(a10, xv.x, fmaf(a11, xv.y, fmaf(w10, hA0, fmaf(w11, hA1, b1))));
            float zB0 = fmaf(a00, xv.z, fmaf(a01, xv.w, fmaf(w00, hB0, fmaf(w01, hB1, b0))));
            float zB1 = fmaf(a10, xv.z, fmaf(a11, xv.w, fmaf(w10, hB0, fmaf(w11, hB1, b1))));

            hA0 = exact_tanh(zA0);
            hA1 = exact_tanh(zA1);
            hB0 = exact_tanh(zB0);
            hB1 = exact_tanh(zB1);

            float4 o;
            o.x = sig10(hA0);
            o.y = sig10(hA1);
            o.z = sig10(hB0);
            o.w = sig10(hB1);
            __stcs(ost, o);
            ost += npairs;
        }
    }
    // Tail (T % PF != 0): consume remaining buffered steps.
    for (int i = 0; t < T; ++t, ++i) {
        float4 xv = buf[i];
        float zA0 = fmaf(a00, xv.x, fmaf(a01, xv.y, fmaf(w00, hA0, fmaf(w01, hA1, b0))));
        float zA1 = fmaf(a10, xv.x, fmaf(a11, xv.y, fmaf(w10, hA0, fmaf(w11, hA1, b1))));
        float zB0 = fmaf(a00, xv.z, fmaf(a01, xv.w, fmaf(w00, hB0, fmaf(w01, hB1, b0))));
        float zB1 = fmaf(a10, xv.z, fmaf(a11, xv.w, fmaf(w10, hB0, fmaf(w11, hB1, b1))));
        hA0 = exact_tanh(zA0);
        hA1 = exact_tanh(zA1);
        hB0 = exact_tanh(zB0);
        hB1 = exact_tanh(zB1);
        float4 o;
        o.x = sig10(hA0); o.y = sig10(hA1); o.z = sig10(hB0); o.w = sig10(hB1);
        __stcs(ost, o);
        ost += npairs;
    }

    float4 hf;
    hf.x = hA0; hf.y = hA1; hf.z = hB0; hf.w = hB1;
    hout4[p] = hf;
}

extern "C" void kernel_launch(void* const* d_in, const int* in_sizes, int n_in,
                              void* d_out, int out_size)
{
    const float* x   = (const float*)d_in[0];   // (T, B, 2)
    const float* h0  = (const float*)d_in[1];   // (1, B, 2)
    const float* Wih = (const float*)d_in[2];   // (2, 2)
    const float* Whh = (const float*)d_in[3];   // (2, 2)
    const float* bih = (const float*)d_in[4];   // (2,)
    const float* bhh = (const float*)d_in[5];   // (2,)

    const int BH = in_sizes[1];                 // B * H = B * 2
    const int B  = BH / 2;
    const int T  = in_sizes[0] / BH;            // (T*B*2) / (B*2)

    float* out = (float*)d_out;                 // first T*B*2 elems: out
    float* hout = out + ((size_t)out_size - (size_t)BH);  // last B*2 elems: hidden

    const int npairs = B / 2;                   // float4 granularity (2 batch elems)
    const int threads = 256;
    const int blocks = (npairs + threads - 1) / threads;

    rnn_sigmoid_kernel<<<blocks, threads>>>(
        (const float4*)x, (const float4*)h0,
        Wih, Whh, bih, bhh,
        (float4*)out, (float4*)hout,
        T, npairs);
}

// round 9
// speedup vs baseline: 1.1583x; 1.0775x over previous
#include <cuda_runtime.h>
#include <cstddef>

// Pixel_RNNcontrol: h_t = tanh(x_t @ W_ih^T + h_{t-1} @ W_hh^T + b), out = sigmoid(10 h_t)
// T=128, B=262144, I=H=2. One thread handles 2 batch elements (float4 lanes).
//
// R9: R3 anchor (90.7us, DRAM 72.5%) with PF 4->5. Ceiling probe: chip-wide
// in-flight already exceeds the latency-BW product, so if DRAM doesn't move,
// 5.75TB/s is the mixed read/write stream ceiling and this shape is optimal.
// All other structures (deep regs R4, cp.async R5, TPB=128 R6, TMA R7,
// L2-prefetch R8) regressed.

#define PF 5   // prefetch depth

__device__ __forceinline__ float exact_tanh(float z) {
    // tanh(z) = 1 - 2/(1 + e^{2z}); z bounded (|z| <~ 7) -> no overflow
    float k = 2.885390082f * z;        // 2*log2(e) * z
    float e;
    asm("ex2.approx.f32 %0, %1;" : "=f"(e) : "f"(k));
    float r;
    float d = e + 1.0f;
    asm("rcp.approx.f32 %0, %1;" : "=f"(r) : "f"(d));
    return fmaf(-2.0f, r, 1.0f);
}

__device__ __forceinline__ float sig10(float h) {
    // sigmoid(10h) = 0.5 + 0.5*tanh(5h); HW tanh -> 1 MUFU, error non-accumulating
    float t;
    float a = 5.0f * h;
    asm("tanh.approx.f32 %0, %1;" : "=f"(t) : "f"(a));
    return fmaf(0.5f, t, 0.5f);
}

__global__ void __launch_bounds__(256)
rnn_sigmoid_kernel(const float4* __restrict__ x4,
                   const float4* __restrict__ h04,
                   const float*  __restrict__ Wih,
                   const float*  __restrict__ Whh,
                   const float*  __restrict__ bih,
                   const float*  __restrict__ bhh,
                   float4* __restrict__ out4,
                   float4* __restrict__ hout4,
                   int T, int npairs)
{
    int p = blockIdx.x * blockDim.x + threadIdx.x;
    if (p >= npairs) return;

    // 2x2 weights (row-major). z = x @ W^T  ->  z0 = W[0][0]*x0 + W[0][1]*x1
    const float a00 = Wih[0], a01 = Wih[1], a10 = Wih[2], a11 = Wih[3];
    const float w00 = Whh[0], w01 = Whh[1], w10 = Whh[2], w11 = Whh[3];
    const float b0 = bih[0] + bhh[0];
    const float b1 = bih[1] + bhh[1];

    float4 hv = h04[p];
    float hA0 = hv.x, hA1 = hv.y;   // batch element A
    float hB0 = hv.z, hB1 = hv.w;   // batch element B

    // Prime the pipeline: PF loads in flight before the loop.
    float4 buf[PF];
    #pragma unroll
    for (int i = 0; i < PF; ++i) {
        int ti = (i < T) ? i : (T - 1);
        buf[i] = __ldcs(&x4[(size_t)ti * npairs + p]);
    }

    const float4* xld = x4 + (size_t)PF * npairs + p;   // next load addr (t = PF)
    float4*       ost = out4 + p;                        // store addr (t = 0)

    int t = 0;
    for (; t + PF <= T; t += PF) {
        #pragma unroll
        for (int i = 0; i < PF; ++i) {
            float4 xv = buf[i];
            // issue prefetch for t+i+PF immediately (keeps PF loads in flight)
            if (t + i + PF < T) buf[i] = __ldcs(xld);
            xld += npairs;

            float zA0 = fmaf(a00, xv.x, fmaf(a01, xv.y, fmaf(w00, hA0, fmaf(w01, hA1, b0))));
            float zA1 = fmaf(a10, xv.x, fmaf(a11, xv.y, fmaf(w10, hA0, fmaf(w11, hA1, b1))));
            float zB0 = fmaf(a00, xv.z, fmaf(a01, xv.w, fmaf(w00, hB0, fmaf(w01, hB1, b0))));
            float zB1 = fmaf(a10, xv.z, fmaf(a11, xv.w, fmaf(w10, hB0, fmaf(w11, hB1, b1))));

            hA0 = exact_tanh(zA0);
            hA1 = exact_tanh(zA1);
            hB0 = exact_tanh(zB0);
            hB1 = exact_tanh(zB1);

            float4 o;
            o.x = sig10(hA0);
            o.y = sig10(hA1);
            o.z = sig10(hB0);
            o.w = sig10(hB1);
            __stcs(ost, o);
            ost += npairs;
        }
    }
    // Tail (T % PF != 0): consume remaining buffered steps.
    for (int i = 0; t < T; ++t, ++i) {
        float4 xv = buf[i];
        float zA0 = fmaf(a00, xv.x, fmaf(a01, xv.y, fmaf(w00, hA0, fmaf(w01, hA1, b0))));
        float zA1 = fmaf(a10, xv.x, fmaf(a11, xv.y, fmaf(w10, hA0, fmaf(w11, hA1, b1))));
        float zB0 = fmaf(a00, xv.z, fmaf(a01, xv.w, fmaf(w00, hB0, fmaf(w01, hB1, b0))));
        float zB1 = fmaf(a10, xv.z, fmaf(a11, xv.w, fmaf(w10, hB0, fmaf(w11, hB1, b1))));
        hA0 = exact_tanh(zA0);
        hA1 = exact_tanh(zA1);
        hB0 = exact_tanh(zB0);
        hB1 = exact_tanh(zB1);
        float4 o;
        o.x = sig10(hA0); o.y = sig10(hA1); o.z = sig10(hB0); o.w = sig10(hB1);
        __stcs(ost, o);
        ost += npairs;
    }

    float4 hf;
    hf.x = hA0; hf.y = hA1; hf.z = hB0; hf.w = hB1;
    hout4[p] = hf;
}

extern "C" void kernel_launch(void* const* d_in, const int* in_sizes, int n_in,
                              void* d_out, int out_size)
{
    const float* x   = (const float*)d_in[0];   // (T, B, 2)
    const float* h0  = (const float*)d_in[1];   // (1, B, 2)
    const float* Wih = (const float*)d_in[2];   // (2, 2)
    const float* Whh = (const float*)d_in[3];   // (2, 2)
    const float* bih = (const float*)d_in[4];   // (2,)
    const float* bhh = (const float*)d_in[5];   // (2,)

    const int BH = in_sizes[1];                 // B * H = B * 2
    const int B  = BH / 2;
    const int T  = in_sizes[0] / BH;            // (T*B*2) / (B*2)

    float* out = (float*)d_out;                 // first T*B*2 elems: out
    float* hout = out + ((size_t)out_size - (size_t)BH);  // last B*2 elems: hidden

    const int npairs = B / 2;                   // float4 granularity (2 batch elems)
    const int threads = 256;
    const int blocks = (npairs + threads - 1) / threads;

    rnn_sigmoid_kernel<<<blocks, threads>>>(
        (const float4*)x, (const float4*)h0,
        Wih, Whh, bih, bhh,
        (float4*)out, (float4*)hout,
        T, npairs);
}

// round 10
// speedup vs baseline: 1.2199x; 1.0532x over previous
#include <cuda_runtime.h>
#include <cstddef>

// Pixel_RNNcontrol: h_t = tanh(x_t @ W_ih^T + h_{t-1} @ W_hh^T + b), out = sigmoid(10 h_t)
// T=128, B=262144, I=H=2. One thread handles 2 batch elements (float4 lanes).
//
// R10: R3 anchor (best, 90.7us / DRAM 72.5% / 6.2TB/s incl. writes = ~78% of
// spec, at the mixed-stream ceiling). Changes are issue-overhead shaves only:
// unconditional main loop (no load predicates for 124/128 steps), immediate-
// offset addressing with one pointer bump per PF-group, launch_bounds(256,4).

#define PF 4   // prefetch depth

__device__ __forceinline__ float exact_tanh(float z) {
    // tanh(z) = 1 - 2/(1 + e^{2z}); z bounded (|z| <~ 7) -> no overflow
    float k = 2.885390082f * z;        // 2*log2(e) * z
    float e;
    asm("ex2.approx.f32 %0, %1;" : "=f"(e) : "f"(k));
    float r;
    float d = e + 1.0f;
    asm("rcp.approx.f32 %0, %1;" : "=f"(r) : "f"(d));
    return fmaf(-2.0f, r, 1.0f);
}

__device__ __forceinline__ float sig10(float h) {
    // sigmoid(10h) = 0.5 + 0.5*tanh(5h); HW tanh -> 1 MUFU, error non-accumulating
    float t;
    float a = 5.0f * h;
    asm("tanh.approx.f32 %0, %1;" : "=f"(t) : "f"(a));
    return fmaf(0.5f, t, 0.5f);
}

__global__ void __launch_bounds__(256, 4)
rnn_sigmoid_kernel(const float4* __restrict__ x4,
                   const float4* __restrict__ h04,
                   const float*  __restrict__ Wih,
                   const float*  __restrict__ Whh,
                   const float*  __restrict__ bih,
                   const float*  __restrict__ bhh,
                   float4* __restrict__ out4,
                   float4* __restrict__ hout4,
                   int T, int npairs)
{
    int p = blockIdx.x * blockDim.x + threadIdx.x;
    if (p >= npairs) return;

    // 2x2 weights (row-major). z = x @ W^T  ->  z0 = W[0][0]*x0 + W[0][1]*x1
    const float a00 = Wih[0], a01 = Wih[1], a10 = Wih[2], a11 = Wih[3];
    const float w00 = Whh[0], w01 = Whh[1], w10 = Whh[2], w11 = Whh[3];
    const float b0 = bih[0] + bhh[0];
    const float b1 = bih[1] + bhh[1];

    float4 hv = h04[p];
    float hA0 = hv.x, hA1 = hv.y;   // batch element A
    float hB0 = hv.z, hB1 = hv.w;   // batch element B

    // Prime the pipeline: PF loads in flight before the loop.
    float4 buf[PF];
    #pragma unroll
    for (int i = 0; i < PF; ++i) {
        int ti = (i < T) ? i : (T - 1);
        buf[i] = __ldcs(&x4[(size_t)ti * npairs + p]);
    }

    const float4* xld = x4 + (size_t)PF * npairs + p;   // next load addr (t = PF)
    float4*       ost = out4 + p;                        // store addr (t = 0)
    const size_t  stride = (size_t)npairs;

    int t = 0;

    // Main loop: all PF prefetch loads guaranteed in-range (t + 2*PF <= T).
    for (; t + 2 * PF <= T; t += PF) {
        #pragma unroll
        for (int i = 0; i < PF; ++i) {
            float4 xv = buf[i];
            buf[i] = __ldcs(&xld[(size_t)i * stride]);   // unconditional

            float zA0 = fmaf(a00, xv.x, fmaf(a01, xv.y, fmaf(w00, hA0, fmaf(w01, hA1, b0))));
            float zA1 = fmaf(a10, xv.x, fmaf(a11, xv.y, fmaf(w10, hA0, fmaf(w11, hA1, b1))));
            float zB0 = fmaf(a00, xv.z, fmaf(a01, xv.w, fmaf(w00, hB0, fmaf(w01, hB1, b0))));
            float zB1 = fmaf(a10, xv.z, fmaf(a11, xv.w, fmaf(w10, hB0, fmaf(w11, hB1, b1))));

            hA0 = exact_tanh(zA0);
            hA1 = exact_tanh(zA1);
            hB0 = exact_tanh(zB0);
            hB1 = exact_tanh(zB1);

            float4 o;
            o.x = sig10(hA0);
            o.y = sig10(hA1);
            o.z = sig10(hB0);
            o.w = sig10(hB1);
            __stcs(&ost[(size_t)i * stride], o);
        }
        xld += (size_t)PF * stride;
        ost += (size_t)PF * stride;
    }

    // Cleanup groups: predicated loads (covers the last <= 2*PF-1 steps' groups).
    for (; t + PF <= T; t += PF) {
        #pragma unroll
        for (int i = 0; i < PF; ++i) {
            float4 xv = buf[i];
            if (t + i + PF < T) buf[i] = __ldcs(&xld[(size_t)i * stride]);

            float zA0 = fmaf(a00, xv.x, fmaf(a01, xv.y, fmaf(w00, hA0, fmaf(w01, hA1, b0))));
            float zA1 = fmaf(a10, xv.x, fmaf(a11, xv.y, fmaf(w10, hA0, fmaf(w11, hA1, b1))));
            float zB0 = fmaf(a00, xv.z, fmaf(a01, xv.w, fmaf(w00, hB0, fmaf(w01, hB1, b0))));
            float zB1 = fmaf(a10, xv.z, fmaf(a11, xv.w, fmaf(w10, hB0, fmaf(w11, hB1, b1))));

            hA0 = exact_tanh(zA0);
            hA1 = exact_tanh(zA1);
            hB0 = exact_tanh(zB0);
            hB1 = exact_tanh(zB1);

            float4 o;
            o.x = sig10(hA0);
            o.y = sig10(hA1);
            o.z = sig10(hB0);
            o.w = sig10(hB1);
            __stcs(&ost[(size_t)i * stride], o);
        }
        xld += (size_t)PF * stride;
        ost += (size_t)PF * stride;
    }

    // Scalar tail (T % PF != 0).
    for (int i = 0; t < T; ++t, ++i) {
        float4 xv = buf[i];
        float zA0 = fmaf(a00, xv.x, fmaf(a01, xv.y, fmaf(w00, hA0, fmaf(w01, hA1, b0))));
        float zA1 = fmaf(a10, xv.x, fmaf(a11, xv.y, fmaf(w10, hA0, fmaf(w11, hA1, b1))));
        float zB0 = fmaf(a00, xv.z, fmaf(a01, xv.w, fmaf(w00, hB0, fmaf(w01, hB1, b0))));
        float zB1 = fmaf(a10, xv.z, fmaf(a11, xv.w, fmaf(w10, hB0, fmaf(w11, hB1, b1))));
        hA0 = exact_tanh(zA0);
        hA1 = exact_tanh(zA1);
        hB0 = exact_tanh(zB0);
        hB1 = exact_tanh(zB1);
        float4 o;
        o.x = sig10(hA0); o.y = sig10(hA1); o.z = sig10(hB0); o.w = sig10(hB1);
        __stcs(&ost[(size_t)i * stride], o);
    }

    float4 hf;
    hf.x = hA0; hf.y = hA1; hf.z = hB0; hf.w = hB1;
    hout4[p] = hf;
}

extern "C" void kernel_launch(void* const* d_in, const int* in_sizes, int n_in,
                              void* d_out, int out_size)
{
    const float* x   = (const float*)d_in[0];   // (T, B, 2)
    const float* h0  = (const float*)d_in[1];   // (1, B, 2)
    const float* Wih = (const float*)d_in[2];   // (2, 2)
    const float* Whh = (const float*)d_in[3];   // (2, 2)
    const float* bih = (const float*)d_in[4];   // (2,)
    const float* bhh = (const float*)d_in[5];   // (2,)

    const int BH = in_sizes[1];                 // B * H = B * 2
    const int B  = BH / 2;
    const int T  = in_sizes[0] / BH;            // (T*B*2) / (B*2)

    float* out = (float*)d_out;                 // first T*B*2 elems: out
    float* hout = out + ((size_t)out_size - (size_t)BH);  // last B*2 elems: hidden

    const int npairs = B / 2;                   // float4 granularity (2 batch elems)
    const int threads = 256;
    const int blocks = (npairs + threads - 1) / threads;

    rnn_sigmoid_kernel<<<blocks, threads>>>(
        (const float4*)x, (const float4*)h0,
        Wih, Whh, bih, bhh,
        (float4*)out, (float4*)hout,
        T, npairs);
}